// round 7
// baseline (speedup 1.0000x reference)
#include <cuda_runtime.h>
#include <math.h>
#include <stddef.h>

// Problem constants
#define BB    64
#define TT    1024
#define VOCAB 55
#define EMBED 64
#define HID   128

typedef unsigned long long u64;

// Scratch (device globals: no allocations allowed)
__device__ float g_outs[BB * TT * HID];   // RNN layer-1 outputs (K and V of attention)
__device__ float g_q   [BB * TT * HID];   // Q = outs @ attn_w^T + attn_b
__device__ float g_ctx [BB * TT * HID];   // attention context
__device__ float g_tab0[VOCAB * HID];     // emb[v] @ w_ih0^T + b_ih0 + b_hh0

// ---------------------------------------------------------------------------
// Packed f32x2 helpers (ptxas will not auto-fuse; inline PTX required)
// ---------------------------------------------------------------------------
__device__ __forceinline__ u64 fma2(u64 a, u64 b, u64 c) {
    u64 d; asm("fma.rn.f32x2 %0, %1, %2, %3;" : "=l"(d) : "l"(a), "l"(b), "l"(c));
    return d;
}
__device__ __forceinline__ u64 add2(u64 a, u64 b) {
    u64 d; asm("add.rn.f32x2 %0, %1, %2;" : "=l"(d) : "l"(a), "l"(b));
    return d;
}
__device__ __forceinline__ u64 mul2(u64 a, u64 b) {
    u64 d; asm("mul.rn.f32x2 %0, %1, %2;" : "=l"(d) : "l"(a), "l"(b));
    return d;
}
__device__ __forceinline__ u64 splat2(float v) {
    u64 r; asm("mov.b64 %0, {%1, %1};" : "=l"(r) : "f"(v));
    return r;
}
__device__ __forceinline__ float2 unpack2(u64 v) {
    float lo, hi; asm("mov.b64 {%0, %1}, %2;" : "=f"(lo), "=f"(hi) : "l"(v));
    return make_float2(lo, hi);
}
// tanh via exp: exact at |x| saturation, rel err ~1e-6
__device__ __forceinline__ float tanh_fast(float x) {
    float e = __expf(2.0f * x);
    return 1.0f - __fdividef(2.0f, e + 1.0f);
}

// ---------------------------------------------------------------------------
// Kernel A: precompute layer-0 input table per vocab entry
// ---------------------------------------------------------------------------
__global__ void tab0_kernel(const float* __restrict__ emb,
                            const float* __restrict__ w_ih0,
                            const float* __restrict__ b_ih0,
                            const float* __restrict__ b_hh0) {
    __shared__ float es[EMBED];
    int v = blockIdx.x;
    int i = threadIdx.x;  // 128 threads
    if (i < EMBED) es[i] = emb[v * EMBED + i];
    __syncthreads();
    float acc = b_ih0[i] + b_hh0[i];
    #pragma unroll
    for (int e = 0; e < EMBED; e++)
        acc += es[e] * w_ih0[i * EMBED + e];
    g_tab0[v * HID + i] = acc;
}

// ---------------------------------------------------------------------------
// Kernel B: sequential 2-layer tanh RNN. One block per batch element.
// 256 threads: i = t>>1 (output), q = t&1 (j-half). Weights packed f32x2 in
// registers: 32+64 u64 = 192 float-regs/thread (cap 256 at 256 thr -> no spill)
// ---------------------------------------------------------------------------
__global__ __launch_bounds__(256, 1)
void rnn_kernel(const int*   __restrict__ x,
                const float* __restrict__ w_hh0,
                const float* __restrict__ w_ih1,
                const float* __restrict__ b_ih1,
                const float* __restrict__ w_hh1,
                const float* __restrict__ b_hh1) {
    __shared__ float tab0s[VOCAB * HID];
    __shared__ int   xs[TT];
    __shared__ __align__(16) float h0b[2][HID];
    __shared__ __align__(16) float h1b[2][HID];

    const int b = blockIdx.x;
    const int t = threadIdx.x;
    const int i = t >> 1;
    const int q = t & 1;

    for (int idx = t; idx < VOCAB * HID; idx += 256) tab0s[idx] = g_tab0[idx];
    for (int idx = t; idx < TT;          idx += 256) xs[idx]    = x[b * TT + idx];
    if (t < HID) { h0b[0][t] = 0.f; h0b[1][t] = 0.f; h1b[0][t] = 0.f; h1b[1][t] = 0.f; }

    // Register-resident packed weights
    u64 w0r[32];  // w_hh0[i][q*64 .. q*64+63]
    {
        const ulonglong2* wp = (const ulonglong2*)(w_hh0 + i * HID + q * 64);
        #pragma unroll
        for (int m = 0; m < 16; m++) { ulonglong2 v = wp[m]; w0r[2*m] = v.x; w0r[2*m+1] = v.y; }
    }
    u64 w1r[64];  // q==0: w_ih1 row i; q==1: w_hh1 row i
    {
        const ulonglong2* wp = (const ulonglong2*)((q ? w_hh1 : w_ih1) + i * HID);
        #pragma unroll
        for (int m = 0; m < 32; m++) { ulonglong2 v = wp[m]; w1r[2*m] = v.x; w1r[2*m+1] = v.y; }
    }
    const float c1 = b_ih1[i] + b_hh1[i];

    __syncthreads();

    float* outp = g_outs + (size_t)b * TT * HID;

    #pragma unroll 1
    for (int st = 0; st < TT; st++) {
        const int cur = st & 1, nxt = cur ^ 1;
        const float tb = tab0s[xs[st] * HID + i];  // prefetch (independent)

        // ---- layer 0: h0_new = tanh(tab0[x_t] + h0 @ w_hh0^T) ----
        {
            const ulonglong2* hp = (const ulonglong2*)(&h0b[cur][q * 64]);
            u64 a0 = 0, a1 = 0, a2 = 0, a3 = 0;
            #pragma unroll
            for (int m = 0; m < 16; m += 2) {
                ulonglong2 ha = hp[m], hb = hp[m + 1];
                a0 = fma2(ha.x, w0r[2*m],     a0);
                a1 = fma2(ha.y, w0r[2*m + 1], a1);
                a2 = fma2(hb.x, w0r[2*m + 2], a2);
                a3 = fma2(hb.y, w0r[2*m + 3], a3);
            }
            float2 s = unpack2(add2(add2(a0, a1), add2(a2, a3)));
            float acc = s.x + s.y;
            acc += __shfl_xor_sync(0xffffffffu, acc, 1);
            float h0n = tanh_fast(acc + tb);
            if (!q) h0b[nxt][i] = h0n;
        }
        __syncthreads();

        // ---- layer 1: h1_new = tanh(h0_new @ w_ih1^T + h1 @ w_hh1^T + c1) ----
        {
            const ulonglong2* sp = (const ulonglong2*)(q ? &h1b[cur][0] : &h0b[nxt][0]);
            u64 a0 = 0, a1 = 0, a2 = 0, a3 = 0;
            #pragma unroll
            for (int m = 0; m < 32; m += 2) {
                ulonglong2 ha = sp[m], hb = sp[m + 1];
                a0 = fma2(ha.x, w1r[2*m],     a0);
                a1 = fma2(ha.y, w1r[2*m + 1], a1);
                a2 = fma2(hb.x, w1r[2*m + 2], a2);
                a3 = fma2(hb.y, w1r[2*m + 3], a3);
            }
            float2 s = unpack2(add2(add2(a0, a1), add2(a2, a3)));
            float acc = s.x + s.y;
            acc += __shfl_xor_sync(0xffffffffu, acc, 1);
            float h1n = tanh_fast(acc + c1);
            if (!q) {
                h1b[nxt][i] = h1n;
                outp[st * HID + i] = h1n;
            }
        }
        __syncthreads();
    }
}

// ---------------------------------------------------------------------------
// Kernel C: Q = outs @ attn_w^T + attn_b   (64-row tiles, 4x8 microtiles)
// ---------------------------------------------------------------------------
__global__ __launch_bounds__(256, 1)
void q_kernel(const float* __restrict__ attn_w, const float* __restrict__ attn_b) {
    extern __shared__ float smq[];
    float* wt  = smq;                 // [k=128][i stride 132]
    float* ost = smq + 128 * 132;     // [k=128][r stride 68]
    __shared__ float bs[HID];

    const int t = threadIdx.x;
    const int rg = t >> 4, cg = t & 15;
    const size_t rowbase = (size_t)blockIdx.x * 64;

    for (int idx = t; idx < HID * HID; idx += 256) {
        int i = idx >> 7, k = idx & 127;
        wt[k * 132 + i] = attn_w[idx];
    }
    for (int idx = t; idx < 64 * HID; idx += 256) {
        int r = idx >> 7, k = idx & 127;
        ost[k * 68 + r] = g_outs[(rowbase + r) * HID + k];
    }
    if (t < HID) bs[t] = attn_b[t];
    __syncthreads();

    u64 acc[4][4];
    #pragma unroll
    for (int rr = 0; rr < 4; rr++)
        #pragma unroll
        for (int c = 0; c < 4; c++) acc[rr][c] = 0ull;

    #pragma unroll 2
    for (int k = 0; k < HID; k++) {
        float4 q4 = *(const float4*)(ost + k * 68 + rg * 4);
        ulonglong2 w0 = *(const ulonglong2*)(wt + k * 132 + cg * 8);
        ulonglong2 w1 = *(const ulonglong2*)(wt + k * 132 + cg * 8 + 4);
        float qv[4] = {q4.x, q4.y, q4.z, q4.w};
        #pragma unroll
        for (int rr = 0; rr < 4; rr++) {
            u64 qs = splat2(qv[rr]);
            acc[rr][0] = fma2(qs, w0.x, acc[rr][0]);
            acc[rr][1] = fma2(qs, w0.y, acc[rr][1]);
            acc[rr][2] = fma2(qs, w1.x, acc[rr][2]);
            acc[rr][3] = fma2(qs, w1.y, acc[rr][3]);
        }
    }

    #pragma unroll
    for (int rr = 0; rr < 4; rr++) {
        size_t row = rowbase + rg * 4 + rr;
        float o[8];
        #pragma unroll
        for (int c = 0; c < 4; c++) {
            float2 p = unpack2(acc[rr][c]);
            o[2*c] = p.x + bs[cg * 8 + 2*c];
            o[2*c+1] = p.y + bs[cg * 8 + 2*c + 1];
        }
        *(float4*)(g_q + row * HID + cg * 8)     = make_float4(o[0], o[1], o[2], o[3]);
        *(float4*)(g_q + row * HID + cg * 8 + 4) = make_float4(o[4], o[5], o[6], o[7]);
    }
}

// ---------------------------------------------------------------------------
// Kernel D: causal flash attention (fp32, online softmax, f32x2 packed FMA).
// Block = (qt, b): 64 query rows, loops over qt/2+1 key tiles of 128.
// dyn smem: Qst[128][68], Kst[128][132], Ks[128][132], St[128][68] = 200 KB
// ---------------------------------------------------------------------------
__global__ __launch_bounds__(256, 1)
void attn_kernel() {
    extern __shared__ float sma[];
    float* Qst = sma;                               // [k][r], stride 68
    float* Kst = sma + 128 * 68;                    // [h][s], stride 132
    float* Ks  = sma + 128 * 68 + 128 * 132;        // [s][h], stride 132
    float* St  = sma + 128 * 68 + 2 * 128 * 132;    // [s][r-chunk xor-swizzled], stride 68

    const int qt = blockIdx.x;
    const int b  = blockIdx.y;
    const int t  = threadIdx.x;
    const int rg = t >> 4, cg = t & 15;
    const int qrow0 = qt * 64;
    const float* Qg = g_q    + (size_t)b * TT * HID;
    const float* Og = g_outs + (size_t)b * TT * HID;

    for (int idx = t; idx < 64 * HID; idx += 256) {
        int r = idx >> 7, k = idx & 127;
        Qst[k * 68 + r] = Qg[(qrow0 + r) * HID + k] * 0.08838834764831845f; // 1/sqrt(128)
    }

    float m[4], lsum[4];
    u64 O2[4][4];
    #pragma unroll
    for (int rr = 0; rr < 4; rr++) {
        m[rr] = -1e30f; lsum[rr] = 0.f;
        #pragma unroll
        for (int c = 0; c < 4; c++) O2[rr][c] = 0ull;
    }

    const int nkt = (qt >> 1) + 1;
    for (int kt = 0; kt < nkt; kt++) {
        __syncthreads();  // Qst ready (kt=0) / prior Ks,St reads done
        // Fused load + transpose of K/V tile
        for (int idx = t; idx < 128 * HID; idx += 256) {
            int s = idx >> 7, h = idx & 127;
            float v = Og[(kt * 128 + s) * HID + h];
            Ks [s * 132 + h] = v;
            Kst[h * 132 + s] = v;
        }
        __syncthreads();

        // S = Q K^T: cols packed (pairs of s), rows scalar-splatted
        u64 S2[4][4];
        #pragma unroll
        for (int rr = 0; rr < 4; rr++)
            #pragma unroll
            for (int c = 0; c < 4; c++) S2[rr][c] = 0ull;

        #pragma unroll 2
        for (int k = 0; k < HID; k++) {
            float4 q4 = *(const float4*)(Qst + k * 68 + rg * 4);
            ulonglong2 k0 = *(const ulonglong2*)(Kst + k * 132 + cg * 8);
            ulonglong2 k1 = *(const ulonglong2*)(Kst + k * 132 + cg * 8 + 4);
            float qv[4] = {q4.x, q4.y, q4.z, q4.w};
            #pragma unroll
            for (int rr = 0; rr < 4; rr++) {
                u64 qs = splat2(qv[rr]);
                S2[rr][0] = fma2(qs, k0.x, S2[rr][0]);
                S2[rr][1] = fma2(qs, k0.y, S2[rr][1]);
                S2[rr][2] = fma2(qs, k1.x, S2[rr][2]);
                S2[rr][3] = fma2(qs, k1.y, S2[rr][3]);
            }
        }

        float S[4][8];
        #pragma unroll
        for (int rr = 0; rr < 4; rr++)
            #pragma unroll
            for (int c = 0; c < 4; c++) {
                float2 p = unpack2(S2[rr][c]);
                S[rr][2*c] = p.x; S[rr][2*c+1] = p.y;
            }

        // Causal mask (only diagonal-overlapping tiles)
        if (kt * 128 + 127 > qrow0) {
            #pragma unroll
            for (int rr = 0; rr < 4; rr++) {
                int qi = qrow0 + rg * 4 + rr;
                #pragma unroll
                for (int cc = 0; cc < 8; cc++) {
                    int s = kt * 128 + cg * 8 + cc;
                    if (s > qi) S[rr][cc] = -1e30f;
                }
            }
        }

        // Online softmax (reductions across the 16-lane cg group)
        #pragma unroll
        for (int rr = 0; rr < 4; rr++) {
            float pm = S[rr][0];
            #pragma unroll
            for (int cc = 1; cc < 8; cc++) pm = fmaxf(pm, S[rr][cc]);
            pm = fmaxf(pm, __shfl_xor_sync(0xffffffffu, pm, 1));
            pm = fmaxf(pm, __shfl_xor_sync(0xffffffffu, pm, 2));
            pm = fmaxf(pm, __shfl_xor_sync(0xffffffffu, pm, 4));
            pm = fmaxf(pm, __shfl_xor_sync(0xffffffffu, pm, 8));
            float mn = fmaxf(m[rr], pm);
            float alpha = __expf(m[rr] - mn);
            float rs = 0.f;
            #pragma unroll
            for (int cc = 0; cc < 8; cc++) {
                S[rr][cc] = __expf(S[rr][cc] - mn);
                rs += S[rr][cc];
            }
            rs += __shfl_xor_sync(0xffffffffu, rs, 1);
            rs += __shfl_xor_sync(0xffffffffu, rs, 2);
            rs += __shfl_xor_sync(0xffffffffu, rs, 4);
            rs += __shfl_xor_sync(0xffffffffu, rs, 8);
            lsum[rr] = lsum[rr] * alpha + rs;
            m[rr] = mn;
            u64 as = splat2(alpha);
            #pragma unroll
            for (int c = 0; c < 4; c++) O2[rr][c] = mul2(O2[rr][c], as);
        }

        // Store P transposed with XOR swizzle on the 4-row chunk index:
        // chunk' = rg ^ (s>>3); here s>>3 == cg for our own stores.
        {
            int chw = (rg ^ cg) * 4;
            #pragma unroll
            for (int cc = 0; cc < 8; cc++)
                #pragma unroll
                for (int rr = 0; rr < 4; rr++)
                    St[(cg * 8 + cc) * 68 + chw + rr] = S[rr][cc];
        }
        __syncthreads();

        // O += P @ V  (V = Ks[s][h]; cols packed, P rows splatted)
        #pragma unroll 2
        for (int s = 0; s < 128; s++) {
            float4 p4 = *(const float4*)(St + s * 68 + ((rg ^ (s >> 3)) * 4));
            ulonglong2 v0 = *(const ulonglong2*)(Ks + s * 132 + cg * 8);
            ulonglong2 v1 = *(const ulonglong2*)(Ks + s * 132 + cg * 8 + 4);
            float pv[4] = {p4.x, p4.y, p4.z, p4.w};
            #pragma unroll
            for (int rr = 0; rr < 4; rr++) {
                u64 ps = splat2(pv[rr]);
                O2[rr][0] = fma2(ps, v0.x, O2[rr][0]);
                O2[rr][1] = fma2(ps, v0.y, O2[rr][1]);
                O2[rr][2] = fma2(ps, v1.x, O2[rr][2]);
                O2[rr][3] = fma2(ps, v1.y, O2[rr][3]);
            }
        }
    }

    // Finalize & write context
    float* Cg = g_ctx + (size_t)b * TT * HID;
    #pragma unroll
    for (int rr = 0; rr < 4; rr++) {
        float inv = 1.0f / lsum[rr];
        size_t row = (size_t)qrow0 + rg * 4 + rr;
        float o[8];
        #pragma unroll
        for (int c = 0; c < 4; c++) {
            float2 p = unpack2(O2[rr][c]);
            o[2*c] = p.x * inv; o[2*c+1] = p.y * inv;
        }
        *(float4*)(Cg + row * HID + cg * 8)     = make_float4(o[0], o[1], o[2], o[3]);
        *(float4*)(Cg + row * HID + cg * 8 + 4) = make_float4(o[4], o[5], o[6], o[7]);
    }
}

// ---------------------------------------------------------------------------
// Kernel E: logits = [outs, context] @ fc_w^T + fc_b   (16-row blocks)
// ---------------------------------------------------------------------------
__global__ __launch_bounds__(256, 1)
void fc_kernel(const float* __restrict__ fc_w, const float* __restrict__ fc_b,
               float* __restrict__ out) {
    extern __shared__ float smf[];
    float* fwt = smf;                 // [k=256][c stride 56]
    float* xst = smf + 256 * 56;      // [k=256][r stride 20]

    const int t = threadIdx.x;
    const int c  = t & 63;
    const int rg = t >> 6;   // 0..3 -> rows rg*4..rg*4+3
    const size_t rowbase = (size_t)blockIdx.x * 16;

    for (int idx = t; idx < VOCAB * 256; idx += 256) {
        int cc = idx >> 8, k = idx & 255;
        fwt[k * 56 + cc] = fc_w[idx];
    }
    for (int idx = t; idx < 16 * 256; idx += 256) {
        int r = idx >> 8, k = idx & 255;
        size_t row = rowbase + r;
        float v = (k < HID) ? g_outs[row * HID + k] : g_ctx[row * HID + (k - HID)];
        xst[k * 20 + r] = v;
    }
    __syncthreads();

    if (c < VOCAB) {
        float a0 = 0.f, a1 = 0.f, a2 = 0.f, a3 = 0.f;
        #pragma unroll 4
        for (int k = 0; k < 256; k++) {
            float4 x4 = *(const float4*)(xst + k * 20 + rg * 4);
            float wv = fwt[k * 56 + c];
            a0 = fmaf(x4.x, wv, a0);
            a1 = fmaf(x4.y, wv, a1);
            a2 = fmaf(x4.z, wv, a2);
            a3 = fmaf(x4.w, wv, a3);
        }
        float bb = fc_b[c];
        out[(rowbase + rg * 4 + 0) * VOCAB + c] = a0 + bb;
        out[(rowbase + rg * 4 + 1) * VOCAB + c] = a1 + bb;
        out[(rowbase + rg * 4 + 2) * VOCAB + c] = a2 + bb;
        out[(rowbase + rg * 4 + 3) * VOCAB + c] = a3 + bb;
    }
}

// ---------------------------------------------------------------------------
extern "C" void kernel_launch(void* const* d_in, const int* in_sizes, int n_in,
                              void* d_out, int out_size) {
    const int*   x      = (const int*)  d_in[0];
    const float* emb    = (const float*)d_in[1];
    const float* w_ih0  = (const float*)d_in[2];
    const float* b_ih0  = (const float*)d_in[3];
    const float* w_hh0  = (const float*)d_in[4];
    const float* b_hh0  = (const float*)d_in[5];
    const float* w_ih1  = (const float*)d_in[6];
    const float* b_ih1  = (const float*)d_in[7];
    const float* w_hh1  = (const float*)d_in[8];
    const float* b_hh1  = (const float*)d_in[9];
    const float* attn_w = (const float*)d_in[10];
    const float* attn_b = (const float*)d_in[11];
    const float* fc_w   = (const float*)d_in[12];
    const float* fc_b   = (const float*)d_in[13];
    float* out = (float*)d_out;

    const int QSMEM = (128 * 132 + 128 * 68) * 4;                // 102400
    const int ASMEM = (128 * 68 + 2 * 128 * 132 + 128 * 68) * 4; // 204800
    const int FSMEM = (256 * 56 + 256 * 20) * 4;                 // 77824
    cudaFuncSetAttribute((const void*)q_kernel,
                         cudaFuncAttributeMaxDynamicSharedMemorySize, QSMEM);
    cudaFuncSetAttribute((const void*)attn_kernel,
                         cudaFuncAttributeMaxDynamicSharedMemorySize, ASMEM);
    cudaFuncSetAttribute((const void*)fc_kernel,
                         cudaFuncAttributeMaxDynamicSharedMemorySize, FSMEM);

    tab0_kernel<<<VOCAB, HID>>>(emb, w_ih0, b_ih0, b_hh0);
    rnn_kernel<<<BB, 256>>>(x, w_hh0, w_ih1, b_ih1, w_hh1, b_hh1);
    q_kernel<<<(BB * TT) / 64, 256, QSMEM>>>(attn_w, attn_b);
    attn_kernel<<<dim3(TT / 64, BB), 256, ASMEM>>>();
    fc_kernel<<<(BB * TT) / 16, 256, FSMEM>>>(fc_w, fc_b, out);
}

// round 8
// speedup vs baseline: 1.1227x; 1.1227x over previous
#include <cuda_runtime.h>
#include <math.h>
#include <stddef.h>

#define BB    64
#define TT    1024
#define VOCAB 55
#define EMBED 64
#define HID   128

typedef unsigned long long u64;

__device__ float g_outs[BB * TT * HID];
__device__ float g_q   [BB * TT * HID];
__device__ float g_ctx [BB * TT * HID];
__device__ float g_tab0[VOCAB * HID];

// Packed f32x2 helpers
__device__ __forceinline__ u64 fma2(u64 a, u64 b, u64 c) {
    u64 d; asm("fma.rn.f32x2 %0, %1, %2, %3;" : "=l"(d) : "l"(a), "l"(b), "l"(c));
    return d;
}
__device__ __forceinline__ u64 add2(u64 a, u64 b) {
    u64 d; asm("add.rn.f32x2 %0, %1, %2;" : "=l"(d) : "l"(a), "l"(b));
    return d;
}
__device__ __forceinline__ u64 mul2(u64 a, u64 b) {
    u64 d; asm("mul.rn.f32x2 %0, %1, %2;" : "=l"(d) : "l"(a), "l"(b));
    return d;
}
__device__ __forceinline__ u64 splat2(float v) {
    u64 r; asm("mov.b64 %0, {%1, %1};" : "=l"(r) : "f"(v));
    return r;
}
__device__ __forceinline__ float2 unpack2(u64 v) {
    float lo, hi; asm("mov.b64 {%0, %1}, %2;" : "=f"(lo), "=f"(hi) : "l"(v));
    return make_float2(lo, hi);
}
__device__ __forceinline__ float hadd2(u64 v) {
    float2 p = unpack2(v); return p.x + p.y;
}
__device__ __forceinline__ float tanh_fast(float x) {
    float e = __expf(2.0f * x);
    return 1.0f - __fdividef(2.0f, e + 1.0f);
}

// ---------------------------------------------------------------------------
__global__ void tab0_kernel(const float* __restrict__ emb,
                            const float* __restrict__ w_ih0,
                            const float* __restrict__ b_ih0,
                            const float* __restrict__ b_hh0) {
    __shared__ float es[EMBED];
    int v = blockIdx.x;
    int i = threadIdx.x;
    if (i < EMBED) es[i] = emb[v * EMBED + i];
    __syncthreads();
    float acc = b_ih0[i] + b_hh0[i];
    #pragma unroll
    for (int e = 0; e < EMBED; e++)
        acc += es[e] * w_ih0[i * EMBED + e];
    g_tab0[v * HID + i] = acc;
}

// ---------------------------------------------------------------------------
// RNN scan: 256 thr/block, weights in regs (packed f32x2), ONE barrier/step.
// ---------------------------------------------------------------------------
__global__ __launch_bounds__(256, 1)
void rnn_kernel(const int*   __restrict__ x,
                const float* __restrict__ w_hh0,
                const float* __restrict__ w_ih1,
                const float* __restrict__ b_ih1,
                const float* __restrict__ w_hh1,
                const float* __restrict__ b_hh1) {
    __shared__ float tab0s[VOCAB * HID];
    __shared__ int   xs[TT];
    __shared__ __align__(16) float h0b[2][HID];
    __shared__ __align__(16) float h1b[2][HID];

    const int b = blockIdx.x;
    const int t = threadIdx.x;
    const int i = t >> 1;
    const int q = t & 1;

    for (int idx = t; idx < VOCAB * HID; idx += 256) tab0s[idx] = g_tab0[idx];
    for (int idx = t; idx < TT;          idx += 256) xs[idx]    = x[b * TT + idx];
    if (t < HID) { h0b[0][t] = 0.f; h0b[1][t] = 0.f; h1b[0][t] = 0.f; h1b[1][t] = 0.f; }

    u64 w0r[32];
    {
        const ulonglong2* wp = (const ulonglong2*)(w_hh0 + i * HID + q * 64);
        #pragma unroll
        for (int m = 0; m < 16; m++) { ulonglong2 v = wp[m]; w0r[2*m] = v.x; w0r[2*m+1] = v.y; }
    }
    u64 w1r[64];
    {
        const ulonglong2* wp = (const ulonglong2*)((q ? w_hh1 : w_ih1) + i * HID);
        #pragma unroll
        for (int m = 0; m < 32; m++) { ulonglong2 v = wp[m]; w1r[2*m] = v.x; w1r[2*m+1] = v.y; }
    }
    const float c1 = b_ih1[i] + b_hh1[i];

    __syncthreads();

    float* outp = g_outs + (size_t)b * TT * HID;

    #pragma unroll 1
    for (int st = 0; st < TT; st++) {
        const int cur = st & 1, nxt = cur ^ 1;
        const float tb = tab0s[xs[st] * HID + i];

        {   // layer 0
            const ulonglong2* hp = (const ulonglong2*)(&h0b[cur][q * 64]);
            u64 a0 = 0, a1 = 0, a2 = 0, a3 = 0;
            #pragma unroll
            for (int m = 0; m < 16; m += 2) {
                ulonglong2 ha = hp[m], hb = hp[m + 1];
                a0 = fma2(ha.x, w0r[2*m],     a0);
                a1 = fma2(ha.y, w0r[2*m + 1], a1);
                a2 = fma2(hb.x, w0r[2*m + 2], a2);
                a3 = fma2(hb.y, w0r[2*m + 3], a3);
            }
            float acc = hadd2(add2(add2(a0, a1), add2(a2, a3)));
            acc += __shfl_xor_sync(0xffffffffu, acc, 1);
            float h0n = tanh_fast(acc + tb);
            if (!q) h0b[nxt][i] = h0n;
        }
        __syncthreads();  // the only barrier per step
        {   // layer 1
            const ulonglong2* sp = (const ulonglong2*)(q ? &h1b[cur][0] : &h0b[nxt][0]);
            u64 a0 = 0, a1 = 0, a2 = 0, a3 = 0;
            #pragma unroll
            for (int m = 0; m < 32; m += 2) {
                ulonglong2 ha = sp[m], hb = sp[m + 1];
                a0 = fma2(ha.x, w1r[2*m],     a0);
                a1 = fma2(ha.y, w1r[2*m + 1], a1);
                a2 = fma2(hb.x, w1r[2*m + 2], a2);
                a3 = fma2(hb.y, w1r[2*m + 3], a3);
            }
            float acc = hadd2(add2(add2(a0, a1), add2(a2, a3)));
            acc += __shfl_xor_sync(0xffffffffu, acc, 1);
            float h1n = tanh_fast(acc + c1);
            if (!q) {
                h1b[nxt][i] = h1n;
                outp[st * HID + i] = h1n;
            }
        }
        // next step's barrier orders all remaining pairs (double-buffered)
    }
}

// ---------------------------------------------------------------------------
// Q projection
// ---------------------------------------------------------------------------
__global__ __launch_bounds__(256, 1)
void q_kernel(const float* __restrict__ attn_w, const float* __restrict__ attn_b) {
    extern __shared__ float smq[];
    float* wt  = smq;                 // [k=128][i stride 132]
    float* ost = smq + 128 * 132;     // [k=128][r stride 68]
    __shared__ float bs[HID];

    const int t = threadIdx.x;
    const int rg = t >> 4, cg = t & 15;
    const size_t rowbase = (size_t)blockIdx.x * 64;

    for (int idx = t; idx < HID * HID; idx += 256) {
        int i = idx >> 7, k = idx & 127;
        wt[k * 132 + i] = attn_w[idx];
    }
    for (int idx = t; idx < 64 * HID; idx += 256) {
        int r = idx >> 7, k = idx & 127;
        ost[k * 68 + r] = g_outs[(rowbase + r) * HID + k];
    }
    if (t < HID) bs[t] = attn_b[t];
    __syncthreads();

    u64 acc[4][4];
    #pragma unroll
    for (int rr = 0; rr < 4; rr++)
        #pragma unroll
        for (int c = 0; c < 4; c++) acc[rr][c] = 0ull;

    #pragma unroll 2
    for (int k = 0; k < HID; k++) {
        float4 q4 = *(const float4*)(ost + k * 68 + rg * 4);
        ulonglong2 w0 = *(const ulonglong2*)(wt + k * 132 + cg * 8);
        ulonglong2 w1 = *(const ulonglong2*)(wt + k * 132 + cg * 8 + 4);
        float qv[4] = {q4.x, q4.y, q4.z, q4.w};
        #pragma unroll
        for (int rr = 0; rr < 4; rr++) {
            u64 qs = splat2(qv[rr]);
            acc[rr][0] = fma2(qs, w0.x, acc[rr][0]);
            acc[rr][1] = fma2(qs, w0.y, acc[rr][1]);
            acc[rr][2] = fma2(qs, w1.x, acc[rr][2]);
            acc[rr][3] = fma2(qs, w1.y, acc[rr][3]);
        }
    }

    #pragma unroll
    for (int rr = 0; rr < 4; rr++) {
        size_t row = rowbase + rg * 4 + rr;
        float o[8];
        #pragma unroll
        for (int c = 0; c < 4; c++) {
            float2 p = unpack2(acc[rr][c]);
            o[2*c]   = p.x + bs[cg * 8 + 2*c];
            o[2*c+1] = p.y + bs[cg * 8 + 2*c + 1];
        }
        *(float4*)(g_q + row * HID + cg * 8)     = make_float4(o[0], o[1], o[2], o[3]);
        *(float4*)(g_q + row * HID + cg * 8 + 4) = make_float4(o[4], o[5], o[6], o[7]);
    }
}

// ---------------------------------------------------------------------------
// Flash attention, 2 CTAs/SM. Block (qt 0..15, b): 64 q-rows, 64-key tiles.
// smem 82KB: Qs[64][130], Ks[64][130], St[64][68] (stride 130 => conflict-free
// u64 LDS: 65*s mod 16 is a permutation). S-GEMM h-vectorized (no splats).
// ---------------------------------------------------------------------------
#define KROW  130
#define KROW2 65

__global__ __launch_bounds__(256, 2)
void attn_kernel() {
    extern __shared__ float sma[];
    float* Qs = sma;                     // [64][130]
    float* Ks = sma + 64 * KROW;         // [64][130]
    float* St = sma + 2 * 64 * KROW;     // [64][68], xor-swizzled 4-row chunks
    u64* Qs2 = (u64*)Qs;
    u64* Ks2 = (u64*)Ks;

    const int qt = blockIdx.x;
    const int b  = blockIdx.y;
    const int t  = threadIdx.x;
    const int rg = t >> 4, cg = t & 15;
    const int qrow0 = qt * 64;
    const float* Qg = g_q    + (size_t)b * TT * HID;
    const float* Og = g_outs + (size_t)b * TT * HID;

    {   // fill Qs (u64, fold scale)
        const u64 sc2 = splat2(0.08838834764831845f);
        const u64* Qg2 = (const u64*)Qg;
        #pragma unroll
        for (int j = 0; j < 16; j++) {
            int idx2 = t + 256 * j;
            int r = idx2 >> 6, h2 = idx2 & 63;
            u64 v = Qg2[(size_t)(qrow0 + r) * (HID/2) + h2];
            Qs2[r * KROW2 + h2] = mul2(v, sc2);
        }
    }

    float m[4], lsum[4];
    u64 O2[4][4];                        // [row][h-pair j], pair = cg + 16j
    #pragma unroll
    for (int rr = 0; rr < 4; rr++) {
        m[rr] = -1e30f; lsum[rr] = 0.f;
        #pragma unroll
        for (int j = 0; j < 4; j++) O2[rr][j] = 0ull;
    }

    const int nkt = qt + 1;
    for (int kt = 0; kt < nkt; kt++) {
        __syncthreads();
        {   // fill K/V tile
            const u64* Og2 = (const u64*)Og;
            #pragma unroll
            for (int j = 0; j < 16; j++) {
                int idx2 = t + 256 * j;
                int s = idx2 >> 6, h2 = idx2 & 63;
                Ks2[s * KROW2 + h2] = Og2[(size_t)(kt * 64 + s) * (HID/2) + h2];
            }
        }
        __syncthreads();

        // S = Q K^T: 4r x 4s per thread (s = 16*cc + cg), h-vectorized
        u64 a2[4][4];
        #pragma unroll
        for (int rr = 0; rr < 4; rr++)
            #pragma unroll
            for (int cc = 0; cc < 4; cc++) a2[rr][cc] = 0ull;
        {
            const u64* Qp = Qs2 + (rg * 4) * KROW2;
            const u64* Kp = Ks2 + cg * KROW2;
            #pragma unroll 1
            for (int h2 = 0; h2 < 64; h2++) {
                u64 q0 = Qp[h2], q1 = Qp[KROW2 + h2], q2 = Qp[2*KROW2 + h2], q3 = Qp[3*KROW2 + h2];
                u64 k0 = Kp[h2], k1 = Kp[16*KROW2 + h2], k2 = Kp[32*KROW2 + h2], k3 = Kp[48*KROW2 + h2];
                a2[0][0] = fma2(q0, k0, a2[0][0]); a2[0][1] = fma2(q0, k1, a2[0][1]);
                a2[0][2] = fma2(q0, k2, a2[0][2]); a2[0][3] = fma2(q0, k3, a2[0][3]);
                a2[1][0] = fma2(q1, k0, a2[1][0]); a2[1][1] = fma2(q1, k1, a2[1][1]);
                a2[1][2] = fma2(q1, k2, a2[1][2]); a2[1][3] = fma2(q1, k3, a2[1][3]);
                a2[2][0] = fma2(q2, k0, a2[2][0]); a2[2][1] = fma2(q2, k1, a2[2][1]);
                a2[2][2] = fma2(q2, k2, a2[2][2]); a2[2][3] = fma2(q2, k3, a2[2][3]);
                a2[3][0] = fma2(q3, k0, a2[3][0]); a2[3][1] = fma2(q3, k1, a2[3][1]);
                a2[3][2] = fma2(q3, k2, a2[3][2]); a2[3][3] = fma2(q3, k3, a2[3][3]);
            }
        }

        float S[4][4];
        #pragma unroll
        for (int rr = 0; rr < 4; rr++)
            #pragma unroll
            for (int cc = 0; cc < 4; cc++) S[rr][cc] = hadd2(a2[rr][cc]);

        if (kt == qt) {  // diagonal tile mask
            #pragma unroll
            for (int rr = 0; rr < 4; rr++) {
                int rl = rg * 4 + rr;
                #pragma unroll
                for (int cc = 0; cc < 4; cc++)
                    if (16 * cc + cg > rl) S[rr][cc] = -1e30f;
            }
        }

        // online softmax (reduce over cg lanes: xor 1,2,4,8 stay in rg half)
        #pragma unroll
        for (int rr = 0; rr < 4; rr++) {
            float pm = fmaxf(fmaxf(S[rr][0], S[rr][1]), fmaxf(S[rr][2], S[rr][3]));
            pm = fmaxf(pm, __shfl_xor_sync(0xffffffffu, pm, 1));
            pm = fmaxf(pm, __shfl_xor_sync(0xffffffffu, pm, 2));
            pm = fmaxf(pm, __shfl_xor_sync(0xffffffffu, pm, 4));
            pm = fmaxf(pm, __shfl_xor_sync(0xffffffffu, pm, 8));
            float mn = fmaxf(m[rr], pm);
            float alpha = __expf(m[rr] - mn);
            float rs = 0.f;
            #pragma unroll
            for (int cc = 0; cc < 4; cc++) {
                S[rr][cc] = __expf(S[rr][cc] - mn);
                rs += S[rr][cc];
            }
            rs += __shfl_xor_sync(0xffffffffu, rs, 1);
            rs += __shfl_xor_sync(0xffffffffu, rs, 2);
            rs += __shfl_xor_sync(0xffffffffu, rs, 4);
            rs += __shfl_xor_sync(0xffffffffu, rs, 8);
            lsum[rr] = lsum[rr] * alpha + rs;
            m[rr] = mn;
            u64 as = splat2(alpha);
            #pragma unroll
            for (int j = 0; j < 4; j++) O2[rr][j] = mul2(O2[rr][j], as);
        }

        {   // store P^T with xor chunk swizzle (s & 15 == cg here)
            int ch = (rg ^ cg) * 4;
            #pragma unroll
            for (int cc = 0; cc < 4; cc++) {
                int s = 16 * cc + cg;
                float* p = St + s * 68 + ch;
                #pragma unroll
                for (int rr = 0; rr < 4; rr++) p[rr] = S[rr][cc];
            }
        }
        __syncthreads();

        // O += P @ V (V rows of Ks; h-pairs cg+16j => conflict-free)
        #pragma unroll 1
        for (int s = 0; s < 64; s++) {
            float4 p4 = *(const float4*)(St + s * 68 + ((rg ^ (s & 15)) * 4));
            const u64* Vp = Ks2 + s * KROW2 + cg;
            u64 v0 = Vp[0], v1 = Vp[16], v2 = Vp[32], v3 = Vp[48];
            u64 p0 = splat2(p4.x), p1 = splat2(p4.y), p2 = splat2(p4.z), p3 = splat2(p4.w);
            O2[0][0] = fma2(p0, v0, O2[0][0]); O2[0][1] = fma2(p0, v1, O2[0][1]);
            O2[0][2] = fma2(p0, v2, O2[0][2]); O2[0][3] = fma2(p0, v3, O2[0][3]);
            O2[1][0] = fma2(p1, v0, O2[1][0]); O2[1][1] = fma2(p1, v1, O2[1][1]);
            O2[1][2] = fma2(p1, v2, O2[1][2]); O2[1][3] = fma2(p1, v3, O2[1][3]);
            O2[2][0] = fma2(p2, v0, O2[2][0]); O2[2][1] = fma2(p2, v1, O2[2][1]);
            O2[2][2] = fma2(p2, v2, O2[2][2]); O2[2][3] = fma2(p2, v3, O2[2][3]);
            O2[3][0] = fma2(p3, v0, O2[3][0]); O2[3][1] = fma2(p3, v1, O2[3][1]);
            O2[3][2] = fma2(p3, v2, O2[3][2]); O2[3][3] = fma2(p3, v3, O2[3][3]);
        }
    }

    // finalize: h-pair j -> cols 2*cg + 32*j
    float* Cg = g_ctx + (size_t)b * TT * HID;
    #pragma unroll
    for (int rr = 0; rr < 4; rr++) {
        u64 inv2 = splat2(1.0f / lsum[rr]);
        size_t row = (size_t)qrow0 + rg * 4 + rr;
        #pragma unroll
        for (int j = 0; j < 4; j++) {
            float2 p = unpack2(mul2(O2[rr][j], inv2));
            *(float2*)(Cg + row * HID + 2 * cg + 32 * j) = p;
        }
    }
}

// ---------------------------------------------------------------------------
// FC to vocab
// ---------------------------------------------------------------------------
__global__ __launch_bounds__(256, 1)
void fc_kernel(const float* __restrict__ fc_w, const float* __restrict__ fc_b,
               float* __restrict__ out) {
    extern __shared__ float smf[];
    float* fwt = smf;                 // [k=256][c stride 56]
    float* xst = smf + 256 * 56;      // [k=256][r stride 20]

    const int t = threadIdx.x;
    const int c  = t & 63;
    const int rg = t >> 6;
    const size_t rowbase = (size_t)blockIdx.x * 16;

    for (int idx = t; idx < VOCAB * 256; idx += 256) {
        int cc = idx >> 8, k = idx & 255;
        fwt[k * 56 + cc] = fc_w[idx];
    }
    for (int idx = t; idx < 16 * 256; idx += 256) {
        int r = idx >> 8, k = idx & 255;
        size_t row = rowbase + r;
        float v = (k < HID) ? g_outs[row * HID + k] : g_ctx[row * HID + (k - HID)];
        xst[k * 20 + r] = v;
    }
    __syncthreads();

    if (c < VOCAB) {
        float a0 = 0.f, a1 = 0.f, a2 = 0.f, a3 = 0.f;
        #pragma unroll 4
        for (int k = 0; k < 256; k++) {
            float4 x4 = *(const float4*)(xst + k * 20 + rg * 4);
            float wv = fwt[k * 56 + c];
            a0 = fmaf(x4.x, wv, a0);
            a1 = fmaf(x4.y, wv, a1);
            a2 = fmaf(x4.z, wv, a2);
            a3 = fmaf(x4.w, wv, a3);
        }
        float bb = fc_b[c];
        out[(rowbase + rg * 4 + 0) * VOCAB + c] = a0 + bb;
        out[(rowbase + rg * 4 + 1) * VOCAB + c] = a1 + bb;
        out[(rowbase + rg * 4 + 2) * VOCAB + c] = a2 + bb;
        out[(rowbase + rg * 4 + 3) * VOCAB + c] = a3 + bb;
    }
}

// ---------------------------------------------------------------------------
extern "C" void kernel_launch(void* const* d_in, const int* in_sizes, int n_in,
                              void* d_out, int out_size) {
    const int*   x      = (const int*)  d_in[0];
    const float* emb    = (const float*)d_in[1];
    const float* w_ih0  = (const float*)d_in[2];
    const float* b_ih0  = (const float*)d_in[3];
    const float* w_hh0  = (const float*)d_in[4];
    const float* b_hh0  = (const float*)d_in[5];
    const float* w_ih1  = (const float*)d_in[6];
    const float* b_ih1  = (const float*)d_in[7];
    const float* w_hh1  = (const float*)d_in[8];
    const float* b_hh1  = (const float*)d_in[9];
    const float* attn_w = (const float*)d_in[10];
    const float* attn_b = (const float*)d_in[11];
    const float* fc_w   = (const float*)d_in[12];
    const float* fc_b   = (const float*)d_in[13];
    float* out = (float*)d_out;

    const int QSMEM = (128 * 132 + 128 * 68) * 4;      // 102400
    const int ASMEM = (2 * 64 * KROW + 64 * 68) * 4;   // 83968
    const int FSMEM = (256 * 56 + 256 * 20) * 4;       // 77824
    cudaFuncSetAttribute((const void*)q_kernel,
                         cudaFuncAttributeMaxDynamicSharedMemorySize, QSMEM);
    cudaFuncSetAttribute((const void*)attn_kernel,
                         cudaFuncAttributeMaxDynamicSharedMemorySize, ASMEM);
    cudaFuncSetAttribute((const void*)fc_kernel,
                         cudaFuncAttributeMaxDynamicSharedMemorySize, FSMEM);

    tab0_kernel<<<VOCAB, HID>>>(emb, w_ih0, b_ih0, b_hh0);
    rnn_kernel<<<BB, 256>>>(x, w_hh0, w_ih1, b_ih1, w_hh1, b_hh1);
    q_kernel<<<(BB * TT) / 64, 256, QSMEM>>>(attn_w, attn_b);
    attn_kernel<<<dim3(TT / 64, BB), 256, ASMEM>>>();
    fc_kernel<<<(BB * TT) / 16, 256, FSMEM>>>(fc_w, fc_b, out);
}

// round 9
// speedup vs baseline: 1.3061x; 1.1634x over previous
#include <cuda_runtime.h>
#include <math.h>
#include <stddef.h>

#define BB    64
#define TT    1024
#define VOCAB 55
#define EMBED 64
#define HID   128

typedef unsigned long long u64;

__device__ float g_outs[BB * TT * HID];
__device__ float g_q   [BB * TT * HID];
__device__ float g_ctx [BB * TT * HID];
__device__ float g_tab0[VOCAB * HID];

// Packed f32x2 helpers
__device__ __forceinline__ u64 fma2(u64 a, u64 b, u64 c) {
    u64 d; asm("fma.rn.f32x2 %0, %1, %2, %3;" : "=l"(d) : "l"(a), "l"(b), "l"(c));
    return d;
}
__device__ __forceinline__ u64 add2(u64 a, u64 b) {
    u64 d; asm("add.rn.f32x2 %0, %1, %2;" : "=l"(d) : "l"(a), "l"(b));
    return d;
}
__device__ __forceinline__ u64 mul2(u64 a, u64 b) {
    u64 d; asm("mul.rn.f32x2 %0, %1, %2;" : "=l"(d) : "l"(a), "l"(b));
    return d;
}
__device__ __forceinline__ u64 splat2(float v) {
    u64 r; asm("mov.b64 %0, {%1, %1};" : "=l"(r) : "f"(v));
    return r;
}
__device__ __forceinline__ float2 unpack2(u64 v) {
    float lo, hi; asm("mov.b64 {%0, %1}, %2;" : "=f"(lo), "=f"(hi) : "l"(v));
    return make_float2(lo, hi);
}
__device__ __forceinline__ float hadd2(u64 v) {
    float2 p = unpack2(v); return p.x + p.y;
}
__device__ __forceinline__ float tanh_fast(float x) {
    float e = __expf(2.0f * x);
    return 1.0f - __fdividef(2.0f, e + 1.0f);
}

#define BAR_SYNC(id, cnt)   asm volatile("bar.sync %0, %1;"   :: "r"(id), "r"(cnt) : "memory")
#define BAR_ARRIVE(id, cnt) asm volatile("bar.arrive %0, %1;" :: "r"(id), "r"(cnt) : "memory")

// ---------------------------------------------------------------------------
__global__ void tab0_kernel(const float* __restrict__ emb,
                            const float* __restrict__ w_ih0,
                            const float* __restrict__ b_ih0,
                            const float* __restrict__ b_hh0) {
    __shared__ float es[EMBED];
    int v = blockIdx.x;
    int i = threadIdx.x;
    if (i < EMBED) es[i] = emb[v * EMBED + i];
    __syncthreads();
    float acc = b_ih0[i] + b_hh0[i];
    #pragma unroll
    for (int e = 0; e < EMBED; e++)
        acc += es[e] * w_ih0[i * EMBED + e];
    g_tab0[v * HID + i] = acc;
}

// ---------------------------------------------------------------------------
// Warp-specialized RNN scan. 384 threads/block, one block per batch.
//   Group A (thr 0..127):  layer0 producer. Thread i owns w_hh0 row i (64 u64).
//     h0(t) depends only on h0(t-1): A runs ahead (<=2 steps, h0b double buf).
//   Group B (thr 128..383): layer1 consumer. idx = t-128, i = idx>>1, q = idx&1.
//     q=0: w_ih1 row i dot h0(t);  q=1: w_hh1 row i dot h1(t-1); shfl-combine.
// Named barriers (parity-alternated to keep single-counter semantics safe):
//   data  A->B: id 2+(st&1), count 384  (A arrives, B syncs)
//   credit B->A: id 4+(st&1), count 384 (B arrives, A syncs at st+2)
//   A-internal: id 1 cnt 128; B-internal: id 6 cnt 256.
// ---------------------------------------------------------------------------
__global__ __launch_bounds__(384, 1)
void rnn_kernel(const int*   __restrict__ x,
                const float* __restrict__ w_hh0,
                const float* __restrict__ w_ih1,
                const float* __restrict__ b_ih1,
                const float* __restrict__ w_hh1,
                const float* __restrict__ b_hh1) {
    __shared__ float tab0s[VOCAB * HID];
    __shared__ int   xs[TT];
    __shared__ __align__(16) float h0b[2][HID];
    __shared__ __align__(16) float h1b[2][HID];

    const int b = blockIdx.x;
    const int t = threadIdx.x;

    for (int idx = t; idx < VOCAB * HID; idx += 384) tab0s[idx] = g_tab0[idx];
    for (int idx = t; idx < TT;          idx += 384) xs[idx]    = x[b * TT + idx];
    if (t < HID) { h0b[0][t] = 0.f; h0b[1][t] = 0.f; h1b[0][t] = 0.f; h1b[1][t] = 0.f; }

    // Uniform weight load: one full 128-float row per thread (64 u64 regs).
    const int  bidx = t - 128;
    const int  bi   = bidx >> 1;        // valid for t >= 128
    const int  bq   = bidx & 1;
    const float* wsrc;
    if (t < 128)      wsrc = w_hh0 + t * HID;
    else if (bq == 0) wsrc = w_ih1 + bi * HID;
    else              wsrc = w_hh1 + bi * HID;

    u64 wreg[64];
    {
        const ulonglong2* wp = (const ulonglong2*)wsrc;
        #pragma unroll
        for (int m = 0; m < 32; m++) { ulonglong2 v = wp[m]; wreg[2*m] = v.x; wreg[2*m+1] = v.y; }
    }

    __syncthreads();

    float* outp = g_outs + (size_t)b * TT * HID;

    if (t < 128) {
        // ---------------- Group A: layer0 producer ----------------
        #pragma unroll 1
        for (int st = 0; st < TT; st++) {
            const int p = st & 1, prev = p ^ 1;
            if (st >= 2) BAR_SYNC(4 + p, 384);           // B consumed slot p @ st-2
            const float tb = tab0s[xs[st] * HID + t];
            const ulonglong2* hp = (const ulonglong2*)(&h0b[prev][0]);
            u64 a0 = 0, a1 = 0, a2 = 0, a3 = 0;
            #pragma unroll
            for (int m = 0; m < 16; m++) {
                ulonglong2 va = hp[2*m], vb = hp[2*m+1];
                a0 = fma2(va.x, wreg[4*m],     a0);
                a1 = fma2(va.y, wreg[4*m + 1], a1);
                a2 = fma2(vb.x, wreg[4*m + 2], a2);
                a3 = fma2(vb.y, wreg[4*m + 3], a3);
            }
            float acc = hadd2(add2(add2(a0, a1), add2(a2, a3)));
            float h0n = tanh_fast(acc + tb);
            h0b[p][t] = h0n;
            BAR_ARRIVE(2 + p, 384);                      // h0(st) ready for B
            BAR_SYNC(1, 128);                            // A-internal ordering
        }
    } else {
        // ---------------- Group B: layer1 consumer ----------------
        const float c1 = b_ih1[bi] + b_hh1[bi];
        #pragma unroll 1
        for (int st = 0; st < TT; st++) {
            const int p = st & 1, prev = p ^ 1;
            BAR_SYNC(2 + p, 384);                        // wait h0(st)
            const ulonglong2* sp = (const ulonglong2*)(bq ? &h1b[prev][0] : &h0b[p][0]);
            u64 a0 = 0, a1 = 0, a2 = 0, a3 = 0;
            #pragma unroll
            for (int m = 0; m < 16; m++) {
                ulonglong2 va = sp[2*m], vb = sp[2*m+1];
                a0 = fma2(va.x, wreg[4*m],     a0);
                a1 = fma2(va.y, wreg[4*m + 1], a1);
                a2 = fma2(vb.x, wreg[4*m + 2], a2);
                a3 = fma2(vb.y, wreg[4*m + 3], a3);
            }
            float acc = hadd2(add2(add2(a0, a1), add2(a2, a3)));
            acc += __shfl_xor_sync(0xffffffffu, acc, 1);
            BAR_ARRIVE(4 + p, 384);                      // credit: slot p consumed
            float h1n = tanh_fast(acc + c1);
            if (!bq) {
                h1b[p][bi] = h1n;
                outp[st * HID + bi] = h1n;
            }
            BAR_SYNC(6, 256);                            // B-internal ordering
        }
    }
}

// ---------------------------------------------------------------------------
// Q projection
// ---------------------------------------------------------------------------
__global__ __launch_bounds__(256, 1)
void q_kernel(const float* __restrict__ attn_w, const float* __restrict__ attn_b) {
    extern __shared__ float smq[];
    float* wt  = smq;                 // [k=128][i stride 132]
    float* ost = smq + 128 * 132;     // [k=128][r stride 68]
    __shared__ float bs[HID];

    const int t = threadIdx.x;
    const int rg = t >> 4, cg = t & 15;
    const size_t rowbase = (size_t)blockIdx.x * 64;

    for (int idx = t; idx < HID * HID; idx += 256) {
        int i = idx >> 7, k = idx & 127;
        wt[k * 132 + i] = attn_w[idx];
    }
    for (int idx = t; idx < 64 * HID; idx += 256) {
        int r = idx >> 7, k = idx & 127;
        ost[k * 68 + r] = g_outs[(rowbase + r) * HID + k];
    }
    if (t < HID) bs[t] = attn_b[t];
    __syncthreads();

    u64 acc[4][4];
    #pragma unroll
    for (int rr = 0; rr < 4; rr++)
        #pragma unroll
        for (int c = 0; c < 4; c++) acc[rr][c] = 0ull;

    #pragma unroll 2
    for (int k = 0; k < HID; k++) {
        float4 q4 = *(const float4*)(ost + k * 68 + rg * 4);
        ulonglong2 w0 = *(const ulonglong2*)(wt + k * 132 + cg * 8);
        ulonglong2 w1 = *(const ulonglong2*)(wt + k * 132 + cg * 8 + 4);
        float qv[4] = {q4.x, q4.y, q4.z, q4.w};
        #pragma unroll
        for (int rr = 0; rr < 4; rr++) {
            u64 qs = splat2(qv[rr]);
            acc[rr][0] = fma2(qs, w0.x, acc[rr][0]);
            acc[rr][1] = fma2(qs, w0.y, acc[rr][1]);
            acc[rr][2] = fma2(qs, w1.x, acc[rr][2]);
            acc[rr][3] = fma2(qs, w1.y, acc[rr][3]);
        }
    }

    #pragma unroll
    for (int rr = 0; rr < 4; rr++) {
        size_t row = rowbase + rg * 4 + rr;
        float o[8];
        #pragma unroll
        for (int c = 0; c < 4; c++) {
            float2 p = unpack2(acc[rr][c]);
            o[2*c]   = p.x + bs[cg * 8 + 2*c];
            o[2*c+1] = p.y + bs[cg * 8 + 2*c + 1];
        }
        *(float4*)(g_q + row * HID + cg * 8)     = make_float4(o[0], o[1], o[2], o[3]);
        *(float4*)(g_q + row * HID + cg * 8 + 4) = make_float4(o[4], o[5], o[6], o[7]);
    }
}

// ---------------------------------------------------------------------------
// Flash attention, 2 CTAs/SM (unchanged from round 8 winner).
// ---------------------------------------------------------------------------
#define KROW  130
#define KROW2 65

__global__ __launch_bounds__(256, 2)
void attn_kernel() {
    extern __shared__ float sma[];
    float* Qs = sma;                     // [64][130]
    float* Ks = sma + 64 * KROW;         // [64][130]
    float* St = sma + 2 * 64 * KROW;     // [64][68], xor-swizzled 4-row chunks
    u64* Qs2 = (u64*)Qs;
    u64* Ks2 = (u64*)Ks;

    const int qt = blockIdx.x;
    const int b  = blockIdx.y;
    const int t  = threadIdx.x;
    const int rg = t >> 4, cg = t & 15;
    const int qrow0 = qt * 64;
    const float* Qg = g_q    + (size_t)b * TT * HID;
    const float* Og = g_outs + (size_t)b * TT * HID;

    {
        const u64 sc2 = splat2(0.08838834764831845f);
        const u64* Qg2 = (const u64*)Qg;
        #pragma unroll
        for (int j = 0; j < 16; j++) {
            int idx2 = t + 256 * j;
            int r = idx2 >> 6, h2 = idx2 & 63;
            u64 v = Qg2[(size_t)(qrow0 + r) * (HID/2) + h2];
            Qs2[r * KROW2 + h2] = mul2(v, sc2);
        }
    }

    float m[4], lsum[4];
    u64 O2[4][4];
    #pragma unroll
    for (int rr = 0; rr < 4; rr++) {
        m[rr] = -1e30f; lsum[rr] = 0.f;
        #pragma unroll
        for (int j = 0; j < 4; j++) O2[rr][j] = 0ull;
    }

    const int nkt = qt + 1;
    for (int kt = 0; kt < nkt; kt++) {
        __syncthreads();
        {
            const u64* Og2 = (const u64*)Og;
            #pragma unroll
            for (int j = 0; j < 16; j++) {
                int idx2 = t + 256 * j;
                int s = idx2 >> 6, h2 = idx2 & 63;
                Ks2[s * KROW2 + h2] = Og2[(size_t)(kt * 64 + s) * (HID/2) + h2];
            }
        }
        __syncthreads();

        u64 a2[4][4];
        #pragma unroll
        for (int rr = 0; rr < 4; rr++)
            #pragma unroll
            for (int cc = 0; cc < 4; cc++) a2[rr][cc] = 0ull;
        {
            const u64* Qp = Qs2 + (rg * 4) * KROW2;
            const u64* Kp = Ks2 + cg * KROW2;
            #pragma unroll 1
            for (int h2 = 0; h2 < 64; h2++) {
                u64 q0 = Qp[h2], q1 = Qp[KROW2 + h2], q2 = Qp[2*KROW2 + h2], q3 = Qp[3*KROW2 + h2];
                u64 k0 = Kp[h2], k1 = Kp[16*KROW2 + h2], k2 = Kp[32*KROW2 + h2], k3 = Kp[48*KROW2 + h2];
                a2[0][0] = fma2(q0, k0, a2[0][0]); a2[0][1] = fma2(q0, k1, a2[0][1]);
                a2[0][2] = fma2(q0, k2, a2[0][2]); a2[0][3] = fma2(q0, k3, a2[0][3]);
                a2[1][0] = fma2(q1, k0, a2[1][0]); a2[1][1] = fma2(q1, k1, a2[1][1]);
                a2[1][2] = fma2(q1, k2, a2[1][2]); a2[1][3] = fma2(q1, k3, a2[1][3]);
                a2[2][0] = fma2(q2, k0, a2[2][0]); a2[2][1] = fma2(q2, k1, a2[2][1]);
                a2[2][2] = fma2(q2, k2, a2[2][2]); a2[2][3] = fma2(q2, k3, a2[2][3]);
                a2[3][0] = fma2(q3, k0, a2[3][0]); a2[3][1] = fma2(q3, k1, a2[3][1]);
                a2[3][2] = fma2(q3, k2, a2[3][2]); a2[3][3] = fma2(q3, k3, a2[3][3]);
            }
        }

        float S[4][4];
        #pragma unroll
        for (int rr = 0; rr < 4; rr++)
            #pragma unroll
            for (int cc = 0; cc < 4; cc++) S[rr][cc] = hadd2(a2[rr][cc]);

        if (kt == qt) {
            #pragma unroll
            for (int rr = 0; rr < 4; rr++) {
                int rl = rg * 4 + rr;
                #pragma unroll
                for (int cc = 0; cc < 4; cc++)
                    if (16 * cc + cg > rl) S[rr][cc] = -1e30f;
            }
        }

        #pragma unroll
        for (int rr = 0; rr < 4; rr++) {
            float pm = fmaxf(fmaxf(S[rr][0], S[rr][1]), fmaxf(S[rr][2], S[rr][3]));
            pm = fmaxf(pm, __shfl_xor_sync(0xffffffffu, pm, 1));
            pm = fmaxf(pm, __shfl_xor_sync(0xffffffffu, pm, 2));
            pm = fmaxf(pm, __shfl_xor_sync(0xffffffffu, pm, 4));
            pm = fmaxf(pm, __shfl_xor_sync(0xffffffffu, pm, 8));
            float mn = fmaxf(m[rr], pm);
            float alpha = __expf(m[rr] - mn);
            float rs = 0.f;
            #pragma unroll
            for (int cc = 0; cc < 4; cc++) {
                S[rr][cc] = __expf(S[rr][cc] - mn);
                rs += S[rr][cc];
            }
            rs += __shfl_xor_sync(0xffffffffu, rs, 1);
            rs += __shfl_xor_sync(0xffffffffu, rs, 2);
            rs += __shfl_xor_sync(0xffffffffu, rs, 4);
            rs += __shfl_xor_sync(0xffffffffu, rs, 8);
            lsum[rr] = lsum[rr] * alpha + rs;
            m[rr] = mn;
            u64 as = splat2(alpha);
            #pragma unroll
            for (int j = 0; j < 4; j++) O2[rr][j] = mul2(O2[rr][j], as);
        }

        {
            int ch = (rg ^ cg) * 4;
            #pragma unroll
            for (int cc = 0; cc < 4; cc++) {
                int s = 16 * cc + cg;
                float* p = St + s * 68 + ch;
                #pragma unroll
                for (int rr = 0; rr < 4; rr++) p[rr] = S[rr][cc];
            }
        }
        __syncthreads();

        #pragma unroll 1
        for (int s = 0; s < 64; s++) {
            float4 p4 = *(const float4*)(St + s * 68 + ((rg ^ (s & 15)) * 4));
            const u64* Vp = Ks2 + s * KROW2 + cg;
            u64 v0 = Vp[0], v1 = Vp[16], v2 = Vp[32], v3 = Vp[48];
            u64 p0 = splat2(p4.x), p1 = splat2(p4.y), p2 = splat2(p4.z), p3 = splat2(p4.w);
            O2[0][0] = fma2(p0, v0, O2[0][0]); O2[0][1] = fma2(p0, v1, O2[0][1]);
            O2[0][2] = fma2(p0, v2, O2[0][2]); O2[0][3] = fma2(p0, v3, O2[0][3]);
            O2[1][0] = fma2(p1, v0, O2[1][0]); O2[1][1] = fma2(p1, v1, O2[1][1]);
            O2[1][2] = fma2(p1, v2, O2[1][2]); O2[1][3] = fma2(p1, v3, O2[1][3]);
            O2[2][0] = fma2(p2, v0, O2[2][0]); O2[2][1] = fma2(p2, v1, O2[2][1]);
            O2[2][2] = fma2(p2, v2, O2[2][2]); O2[2][3] = fma2(p2, v3, O2[2][3]);
            O2[3][0] = fma2(p3, v0, O2[3][0]); O2[3][1] = fma2(p3, v1, O2[3][1]);
            O2[3][2] = fma2(p3, v2, O2[3][2]); O2[3][3] = fma2(p3, v3, O2[3][3]);
        }
    }

    float* Cg = g_ctx + (size_t)b * TT * HID;
    #pragma unroll
    for (int rr = 0; rr < 4; rr++) {
        u64 inv2 = splat2(1.0f / lsum[rr]);
        size_t row = (size_t)qrow0 + rg * 4 + rr;
        #pragma unroll
        for (int j = 0; j < 4; j++) {
            float2 p = unpack2(mul2(O2[rr][j], inv2));
            *(float2*)(Cg + row * HID + 2 * cg + 32 * j) = p;
        }
    }
}

// ---------------------------------------------------------------------------
// FC to vocab
// ---------------------------------------------------------------------------
__global__ __launch_bounds__(256, 1)
void fc_kernel(const float* __restrict__ fc_w, const float* __restrict__ fc_b,
               float* __restrict__ out) {
    extern __shared__ float smf[];
    float* fwt = smf;                 // [k=256][c stride 56]
    float* xst = smf + 256 * 56;      // [k=256][r stride 20]

    const int t = threadIdx.x;
    const int c  = t & 63;
    const int rg = t >> 6;
    const size_t rowbase = (size_t)blockIdx.x * 16;

    for (int idx = t; idx < VOCAB * 256; idx += 256) {
        int cc = idx >> 8, k = idx & 255;
        fwt[k * 56 + cc] = fc_w[idx];
    }
    for (int idx = t; idx < 16 * 256; idx += 256) {
        int r = idx >> 8, k = idx & 255;
        size_t row = rowbase + r;
        float v = (k < HID) ? g_outs[row * HID + k] : g_ctx[row * HID + (k - HID)];
        xst[k * 20 + r] = v;
    }
    __syncthreads();

    if (c < VOCAB) {
        float a0 = 0.f, a1 = 0.f, a2 = 0.f, a3 = 0.f;
        #pragma unroll 4
        for (int k = 0; k < 256; k++) {
            float4 x4 = *(const float4*)(xst + k * 20 + rg * 4);
            float wv = fwt[k * 56 + c];
            a0 = fmaf(x4.x, wv, a0);
            a1 = fmaf(x4.y, wv, a1);
            a2 = fmaf(x4.z, wv, a2);
            a3 = fmaf(x4.w, wv, a3);
        }
        float bb = fc_b[c];
        out[(rowbase + rg * 4 + 0) * VOCAB + c] = a0 + bb;
        out[(rowbase + rg * 4 + 1) * VOCAB + c] = a1 + bb;
        out[(rowbase + rg * 4 + 2) * VOCAB + c] = a2 + bb;
        out[(rowbase + rg * 4 + 3) * VOCAB + c] = a3 + bb;
    }
}

// ---------------------------------------------------------------------------
extern "C" void kernel_launch(void* const* d_in, const int* in_sizes, int n_in,
                              void* d_out, int out_size) {
    const int*   x      = (const int*)  d_in[0];
    const float* emb    = (const float*)d_in[1];
    const float* w_ih0  = (const float*)d_in[2];
    const float* b_ih0  = (const float*)d_in[3];
    const float* w_hh0  = (const float*)d_in[4];
    const float* b_hh0  = (const float*)d_in[5];
    const float* w_ih1  = (const float*)d_in[6];
    const float* b_ih1  = (const float*)d_in[7];
    const float* w_hh1  = (const float*)d_in[8];
    const float* b_hh1  = (const float*)d_in[9];
    const float* attn_w = (const float*)d_in[10];
    const float* attn_b = (const float*)d_in[11];
    const float* fc_w   = (const float*)d_in[12];
    const float* fc_b   = (const float*)d_in[13];
    float* out = (float*)d_out;

    const int QSMEM = (128 * 132 + 128 * 68) * 4;      // 102400
    const int ASMEM = (2 * 64 * KROW + 64 * 68) * 4;   // 83968
    const int FSMEM = (256 * 56 + 256 * 20) * 4;       // 77824
    cudaFuncSetAttribute((const void*)q_kernel,
                         cudaFuncAttributeMaxDynamicSharedMemorySize, QSMEM);
    cudaFuncSetAttribute((const void*)attn_kernel,
                         cudaFuncAttributeMaxDynamicSharedMemorySize, ASMEM);
    cudaFuncSetAttribute((const void*)fc_kernel,
                         cudaFuncAttributeMaxDynamicSharedMemorySize, FSMEM);

    tab0_kernel<<<VOCAB, HID>>>(emb, w_ih0, b_ih0, b_hh0);
    rnn_kernel<<<BB, 384>>>(x, w_hh0, w_ih1, b_ih1, w_hh1, b_hh1);
    q_kernel<<<(BB * TT) / 64, 256, QSMEM>>>(attn_w, attn_b);
    attn_kernel<<<dim3(TT / 64, BB), 256, ASMEM>>>();
    fc_kernel<<<(BB * TT) / 16, 256, FSMEM>>>(fc_w, fc_b, out);
}

// round 10
// speedup vs baseline: 1.3460x; 1.0305x over previous
#include <cuda_runtime.h>
#include <math.h>
#include <stddef.h>

#define BB    64
#define TT    1024
#define VOCAB 55
#define EMBED 64
#define HID   128

typedef unsigned long long u64;

__device__ float g_outs[BB * TT * HID];
__device__ float g_q   [BB * TT * HID];
__device__ float g_ctx [BB * TT * HID];
__device__ float g_tab0[VOCAB * HID];

// Packed f32x2 helpers
__device__ __forceinline__ u64 fma2(u64 a, u64 b, u64 c) {
    u64 d; asm("fma.rn.f32x2 %0, %1, %2, %3;" : "=l"(d) : "l"(a), "l"(b), "l"(c));
    return d;
}
__device__ __forceinline__ u64 add2(u64 a, u64 b) {
    u64 d; asm("add.rn.f32x2 %0, %1, %2;" : "=l"(d) : "l"(a), "l"(b));
    return d;
}
__device__ __forceinline__ u64 mul2(u64 a, u64 b) {
    u64 d; asm("mul.rn.f32x2 %0, %1, %2;" : "=l"(d) : "l"(a), "l"(b));
    return d;
}
__device__ __forceinline__ u64 splat2(float v) {
    u64 r; asm("mov.b64 %0, {%1, %1};" : "=l"(r) : "f"(v));
    return r;
}
__device__ __forceinline__ float2 unpack2(u64 v) {
    float lo, hi; asm("mov.b64 {%0, %1}, %2;" : "=f"(lo), "=f"(hi) : "l"(v));
    return make_float2(lo, hi);
}
__device__ __forceinline__ float hadd2(u64 v) {
    float2 p = unpack2(v); return p.x + p.y;
}
__device__ __forceinline__ float tanh_fast(float x) {
    float e = __expf(2.0f * x);
    return 1.0f - __fdividef(2.0f, e + 1.0f);
}

#define BAR_SYNC(id, cnt)   asm volatile("bar.sync %0, %1;"   :: "r"(id), "r"(cnt) : "memory")
#define BAR_ARRIVE(id, cnt) asm volatile("bar.arrive %0, %1;" :: "r"(id), "r"(cnt) : "memory")

// ---------------------------------------------------------------------------
__global__ void tab0_kernel(const float* __restrict__ emb,
                            const float* __restrict__ w_ih0,
                            const float* __restrict__ b_ih0,
                            const float* __restrict__ b_hh0) {
    __shared__ float es[EMBED];
    int v = blockIdx.x;
    int i = threadIdx.x;
    if (i < EMBED) es[i] = emb[v * EMBED + i];
    __syncthreads();
    float acc = b_ih0[i] + b_hh0[i];
    #pragma unroll
    for (int e = 0; e < EMBED; e++)
        acc += es[e] * w_ih0[i * EMBED + e];
    g_tab0[v * HID + i] = acc;
}

// ---------------------------------------------------------------------------
// Warp-specialized RNN scan, 4-slot h0 pipeline.
//   Group A (thr 0..127):  layer0 producer, runs ahead <=4 steps.
//   Group B (thr 128..383): layer1 consumer (q=0: ih1 dot h0; q=1: hh1 dot h1).
// Barriers (all parity-cycled over 4 slots):
//   data  A->B : id 2+(st&3), count 384 (A arrives, B syncs)
//   credit B->A: id 6+(st&3), count 384 (B arrives, A syncs at st+4)
//   A-internal id 1 cnt 128 only for st<4 (later the credit sync orders A).
//   No B-internal barrier: B's data sync each step orders h1b accesses.
// ---------------------------------------------------------------------------
__global__ __launch_bounds__(384, 1)
void rnn_kernel(const int*   __restrict__ x,
                const float* __restrict__ w_hh0,
                const float* __restrict__ w_ih1,
                const float* __restrict__ b_ih1,
                const float* __restrict__ w_hh1,
                const float* __restrict__ b_hh1) {
    __shared__ float tab0s[VOCAB * HID];
    __shared__ int   xs[TT];
    __shared__ __align__(16) float h0b[4][HID];
    __shared__ __align__(16) float h1b[2][HID];

    const int b = blockIdx.x;
    const int t = threadIdx.x;

    for (int idx = t; idx < VOCAB * HID; idx += 384) tab0s[idx] = g_tab0[idx];
    for (int idx = t; idx < TT;          idx += 384) xs[idx]    = x[b * TT + idx];
    if (t < HID) {
        h0b[0][t] = 0.f; h0b[1][t] = 0.f; h0b[2][t] = 0.f; h0b[3][t] = 0.f;
        h1b[0][t] = 0.f; h1b[1][t] = 0.f;
    }

    const int  bidx = t - 128;
    const int  bi   = bidx >> 1;        // valid for t >= 128
    const int  bq   = bidx & 1;
    const float* wsrc;
    if (t < 128)      wsrc = w_hh0 + t * HID;
    else if (bq == 0) wsrc = w_ih1 + bi * HID;
    else              wsrc = w_hh1 + bi * HID;

    u64 wreg[64];
    {
        const ulonglong2* wp = (const ulonglong2*)wsrc;
        #pragma unroll
        for (int m = 0; m < 32; m++) { ulonglong2 v = wp[m]; wreg[2*m] = v.x; wreg[2*m+1] = v.y; }
    }

    __syncthreads();

    float* outp = g_outs + (size_t)b * TT * HID;

    if (t < 128) {
        // ---------------- Group A: layer0 producer ----------------
        #pragma unroll 1
        for (int st = 0; st < TT; st++) {
            const int sl = st & 3, prev = (st - 1) & 3;
            if (st >= 4) BAR_SYNC(6 + sl, 384);          // B consumed slot sl @ st-4
            const float tb = tab0s[xs[st] * HID + t];
            const ulonglong2* hp = (const ulonglong2*)(&h0b[prev][0]);
            u64 a0 = 0, a1 = 0, a2 = 0, a3 = 0;
            #pragma unroll
            for (int m = 0; m < 16; m++) {
                ulonglong2 va = hp[2*m], vb = hp[2*m+1];
                a0 = fma2(va.x, wreg[4*m],     a0);
                a1 = fma2(va.y, wreg[4*m + 1], a1);
                a2 = fma2(vb.x, wreg[4*m + 2], a2);
                a3 = fma2(vb.y, wreg[4*m + 3], a3);
            }
            float acc = hadd2(add2(add2(a0, a1), add2(a2, a3)));
            float h0n = tanh_fast(acc + tb);
            h0b[sl][t] = h0n;
            BAR_ARRIVE(2 + sl, 384);                     // h0(st) ready for B
            if (st < 4) BAR_SYNC(1, 128);                // early-step A ordering
        }
    } else {
        // ---------------- Group B: layer1 consumer ----------------
        const float c1 = b_ih1[bi] + b_hh1[bi];
        #pragma unroll 1
        for (int st = 0; st < TT; st++) {
            const int sl = st & 3, p1 = st & 1;
            BAR_SYNC(2 + sl, 384);                       // wait h0(st)
            const ulonglong2* sp = (const ulonglong2*)(bq ? &h1b[p1 ^ 1][0] : &h0b[sl][0]);
            u64 a0 = 0, a1 = 0, a2 = 0, a3 = 0;
            #pragma unroll
            for (int m = 0; m < 16; m++) {
                ulonglong2 va = sp[2*m], vb = sp[2*m+1];
                a0 = fma2(va.x, wreg[4*m],     a0);
                a1 = fma2(va.y, wreg[4*m + 1], a1);
                a2 = fma2(vb.x, wreg[4*m + 2], a2);
                a3 = fma2(vb.y, wreg[4*m + 3], a3);
            }
            float acc = hadd2(add2(add2(a0, a1), add2(a2, a3)));
            acc += __shfl_xor_sync(0xffffffffu, acc, 1);
            BAR_ARRIVE(6 + sl, 384);                     // credit: slot sl consumed
            float h1n = tanh_fast(acc + c1);
            if (!bq) {
                h1b[p1][bi] = h1n;
                outp[st * HID + bi] = h1n;
            }
            // no B-internal barrier: next step's data sync orders h1b
        }
    }
}

// ---------------------------------------------------------------------------
// Q projection
// ---------------------------------------------------------------------------
__global__ __launch_bounds__(256, 1)
void q_kernel(const float* __restrict__ attn_w, const float* __restrict__ attn_b) {
    extern __shared__ float smq[];
    float* wt  = smq;                 // [k=128][i stride 132]
    float* ost = smq + 128 * 132;     // [k=128][r stride 68]
    __shared__ float bs[HID];

    const int t = threadIdx.x;
    const int rg = t >> 4, cg = t & 15;
    const size_t rowbase = (size_t)blockIdx.x * 64;

    for (int idx = t; idx < HID * HID; idx += 256) {
        int i = idx >> 7, k = idx & 127;
        wt[k * 132 + i] = attn_w[idx];
    }
    for (int idx = t; idx < 64 * HID; idx += 256) {
        int r = idx >> 7, k = idx & 127;
        ost[k * 68 + r] = g_outs[(rowbase + r) * HID + k];
    }
    if (t < HID) bs[t] = attn_b[t];
    __syncthreads();

    u64 acc[4][4];
    #pragma unroll
    for (int rr = 0; rr < 4; rr++)
        #pragma unroll
        for (int c = 0; c < 4; c++) acc[rr][c] = 0ull;

    #pragma unroll 2
    for (int k = 0; k < HID; k++) {
        float4 q4 = *(const float4*)(ost + k * 68 + rg * 4);
        ulonglong2 w0 = *(const ulonglong2*)(wt + k * 132 + cg * 8);
        ulonglong2 w1 = *(const ulonglong2*)(wt + k * 132 + cg * 8 + 4);
        float qv[4] = {q4.x, q4.y, q4.z, q4.w};
        #pragma unroll
        for (int rr = 0; rr < 4; rr++) {
            u64 qs = splat2(qv[rr]);
            acc[rr][0] = fma2(qs, w0.x, acc[rr][0]);
            acc[rr][1] = fma2(qs, w0.y, acc[rr][1]);
            acc[rr][2] = fma2(qs, w1.x, acc[rr][2]);
            acc[rr][3] = fma2(qs, w1.y, acc[rr][3]);
        }
    }

    #pragma unroll
    for (int rr = 0; rr < 4; rr++) {
        size_t row = rowbase + rg * 4 + rr;
        float o[8];
        #pragma unroll
        for (int c = 0; c < 4; c++) {
            float2 p = unpack2(acc[rr][c]);
            o[2*c]   = p.x + bs[cg * 8 + 2*c];
            o[2*c+1] = p.y + bs[cg * 8 + 2*c + 1];
        }
        *(float4*)(g_q + row * HID + cg * 8)     = make_float4(o[0], o[1], o[2], o[3]);
        *(float4*)(g_q + row * HID + cg * 8 + 4) = make_float4(o[4], o[5], o[6], o[7]);
    }
}

// ---------------------------------------------------------------------------
// Flash attention, 2 CTAs/SM, LPT ordering: heaviest q-tiles get lowest bids.
// ---------------------------------------------------------------------------
#define KROW  130
#define KROW2 65

__global__ __launch_bounds__(256, 2)
void attn_kernel() {
    extern __shared__ float sma[];
    float* Qs = sma;                     // [64][130]
    float* Ks = sma + 64 * KROW;         // [64][130]
    float* St = sma + 2 * 64 * KROW;     // [64][68], xor-swizzled 4-row chunks
    u64* Qs2 = (u64*)Qs;
    u64* Ks2 = (u64*)Ks;

    const int qt = 15 - blockIdx.y;      // LPT: qt=15 blocks are bids 0..63
    const int b  = blockIdx.x;
    const int t  = threadIdx.x;
    const int rg = t >> 4, cg = t & 15;
    const int qrow0 = qt * 64;
    const float* Qg = g_q    + (size_t)b * TT * HID;
    const float* Og = g_outs + (size_t)b * TT * HID;

    {
        const u64 sc2 = splat2(0.08838834764831845f);
        const u64* Qg2 = (const u64*)Qg;
        #pragma unroll
        for (int j = 0; j < 16; j++) {
            int idx2 = t + 256 * j;
            int r = idx2 >> 6, h2 = idx2 & 63;
            u64 v = Qg2[(size_t)(qrow0 + r) * (HID/2) + h2];
            Qs2[r * KROW2 + h2] = mul2(v, sc2);
        }
    }

    float m[4], lsum[4];
    u64 O2[4][4];
    #pragma unroll
    for (int rr = 0; rr < 4; rr++) {
        m[rr] = -1e30f; lsum[rr] = 0.f;
        #pragma unroll
        for (int j = 0; j < 4; j++) O2[rr][j] = 0ull;
    }

    const int nkt = qt + 1;
    for (int kt = 0; kt < nkt; kt++) {
        __syncthreads();
        {
            const u64* Og2 = (const u64*)Og;
            #pragma unroll
            for (int j = 0; j < 16; j++) {
                int idx2 = t + 256 * j;
                int s = idx2 >> 6, h2 = idx2 & 63;
                Ks2[s * KROW2 + h2] = Og2[(size_t)(kt * 64 + s) * (HID/2) + h2];
            }
        }
        __syncthreads();

        u64 a2[4][4];
        #pragma unroll
        for (int rr = 0; rr < 4; rr++)
            #pragma unroll
            for (int cc = 0; cc < 4; cc++) a2[rr][cc] = 0ull;
        {
            const u64* Qp = Qs2 + (rg * 4) * KROW2;
            const u64* Kp = Ks2 + cg * KROW2;
            #pragma unroll 1
            for (int h2 = 0; h2 < 64; h2++) {
                u64 q0 = Qp[h2], q1 = Qp[KROW2 + h2], q2 = Qp[2*KROW2 + h2], q3 = Qp[3*KROW2 + h2];
                u64 k0 = Kp[h2], k1 = Kp[16*KROW2 + h2], k2 = Kp[32*KROW2 + h2], k3 = Kp[48*KROW2 + h2];
                a2[0][0] = fma2(q0, k0, a2[0][0]); a2[0][1] = fma2(q0, k1, a2[0][1]);
                a2[0][2] = fma2(q0, k2, a2[0][2]); a2[0][3] = fma2(q0, k3, a2[0][3]);
                a2[1][0] = fma2(q1, k0, a2[1][0]); a2[1][1] = fma2(q1, k1, a2[1][1]);
                a2[1][2] = fma2(q1, k2, a2[1][2]); a2[1][3] = fma2(q1, k3, a2[1][3]);
                a2[2][0] = fma2(q2, k0, a2[2][0]); a2[2][1] = fma2(q2, k1, a2[2][1]);
                a2[2][2] = fma2(q2, k2, a2[2][2]); a2[2][3] = fma2(q2, k3, a2[2][3]);
                a2[3][0] = fma2(q3, k0, a2[3][0]); a2[3][1] = fma2(q3, k1, a2[3][1]);
                a2[3][2] = fma2(q3, k2, a2[3][2]); a2[3][3] = fma2(q3, k3, a2[3][3]);
            }
        }

        float S[4][4];
        #pragma unroll
        for (int rr = 0; rr < 4; rr++)
            #pragma unroll
            for (int cc = 0; cc < 4; cc++) S[rr][cc] = hadd2(a2[rr][cc]);

        if (kt == qt) {
            #pragma unroll
            for (int rr = 0; rr < 4; rr++) {
                int rl = rg * 4 + rr;
                #pragma unroll
                for (int cc = 0; cc < 4; cc++)
                    if (16 * cc + cg > rl) S[rr][cc] = -1e30f;
            }
        }

        #pragma unroll
        for (int rr = 0; rr < 4; rr++) {
            float pm = fmaxf(fmaxf(S[rr][0], S[rr][1]), fmaxf(S[rr][2], S[rr][3]));
            pm = fmaxf(pm, __shfl_xor_sync(0xffffffffu, pm, 1));
            pm = fmaxf(pm, __shfl_xor_sync(0xffffffffu, pm, 2));
            pm = fmaxf(pm, __shfl_xor_sync(0xffffffffu, pm, 4));
            pm = fmaxf(pm, __shfl_xor_sync(0xffffffffu, pm, 8));
            float mn = fmaxf(m[rr], pm);
            float alpha = __expf(m[rr] - mn);
            float rs = 0.f;
            #pragma unroll
            for (int cc = 0; cc < 4; cc++) {
                S[rr][cc] = __expf(S[rr][cc] - mn);
                rs += S[rr][cc];
            }
            rs += __shfl_xor_sync(0xffffffffu, rs, 1);
            rs += __shfl_xor_sync(0xffffffffu, rs, 2);
            rs += __shfl_xor_sync(0xffffffffu, rs, 4);
            rs += __shfl_xor_sync(0xffffffffu, rs, 8);
            lsum[rr] = lsum[rr] * alpha + rs;
            m[rr] = mn;
            u64 as = splat2(alpha);
            #pragma unroll
            for (int j = 0; j < 4; j++) O2[rr][j] = mul2(O2[rr][j], as);
        }

        {
            int ch = (rg ^ cg) * 4;
            #pragma unroll
            for (int cc = 0; cc < 4; cc++) {
                int s = 16 * cc + cg;
                float* p = St + s * 68 + ch;
                #pragma unroll
                for (int rr = 0; rr < 4; rr++) p[rr] = S[rr][cc];
            }
        }
        __syncthreads();

        #pragma unroll 1
        for (int s = 0; s < 64; s++) {
            float4 p4 = *(const float4*)(St + s * 68 + ((rg ^ (s & 15)) * 4));
            const u64* Vp = Ks2 + s * KROW2 + cg;
            u64 v0 = Vp[0], v1 = Vp[16], v2 = Vp[32], v3 = Vp[48];
            u64 p0 = splat2(p4.x), p1 = splat2(p4.y), p2 = splat2(p4.z), p3 = splat2(p4.w);
            O2[0][0] = fma2(p0, v0, O2[0][0]); O2[0][1] = fma2(p0, v1, O2[0][1]);
            O2[0][2] = fma2(p0, v2, O2[0][2]); O2[0][3] = fma2(p0, v3, O2[0][3]);
            O2[1][0] = fma2(p1, v0, O2[1][0]); O2[1][1] = fma2(p1, v1, O2[1][1]);
            O2[1][2] = fma2(p1, v2, O2[1][2]); O2[1][3] = fma2(p1, v3, O2[1][3]);
            O2[2][0] = fma2(p2, v0, O2[2][0]); O2[2][1] = fma2(p2, v1, O2[2][1]);
            O2[2][2] = fma2(p2, v2, O2[2][2]); O2[2][3] = fma2(p2, v3, O2[2][3]);
            O2[3][0] = fma2(p3, v0, O2[3][0]); O2[3][1] = fma2(p3, v1, O2[3][1]);
            O2[3][2] = fma2(p3, v2, O2[3][2]); O2[3][3] = fma2(p3, v3, O2[3][3]);
        }
    }

    float* Cg = g_ctx + (size_t)b * TT * HID;
    #pragma unroll
    for (int rr = 0; rr < 4; rr++) {
        u64 inv2 = splat2(1.0f / lsum[rr]);
        size_t row = (size_t)qrow0 + rg * 4 + rr;
        #pragma unroll
        for (int j = 0; j < 4; j++) {
            float2 p = unpack2(mul2(O2[rr][j], inv2));
            *(float2*)(Cg + row * HID + 2 * cg + 32 * j) = p;
        }
    }
}

// ---------------------------------------------------------------------------
// FC to vocab
// ---------------------------------------------------------------------------
__global__ __launch_bounds__(256, 1)
void fc_kernel(const float* __restrict__ fc_w, const float* __restrict__ fc_b,
               float* __restrict__ out) {
    extern __shared__ float smf[];
    float* fwt = smf;                 // [k=256][c stride 56]
    float* xst = smf + 256 * 56;      // [k=256][r stride 20]

    const int t = threadIdx.x;
    const int c  = t & 63;
    const int rg = t >> 6;
    const size_t rowbase = (size_t)blockIdx.x * 16;

    for (int idx = t; idx < VOCAB * 256; idx += 256) {
        int cc = idx >> 8, k = idx & 255;
        fwt[k * 56 + cc] = fc_w[idx];
    }
    for (int idx = t; idx < 16 * 256; idx += 256) {
        int r = idx >> 8, k = idx & 255;
        size_t row = rowbase + r;
        float v = (k < HID) ? g_outs[row * HID + k] : g_ctx[row * HID + (k - HID)];
        xst[k * 20 + r] = v;
    }
    __syncthreads();

    if (c < VOCAB) {
        float a0 = 0.f, a1 = 0.f, a2 = 0.f, a3 = 0.f;
        #pragma unroll 4
        for (int k = 0; k < 256; k++) {
            float4 x4 = *(const float4*)(xst + k * 20 + rg * 4);
            float wv = fwt[k * 56 + c];
            a0 = fmaf(x4.x, wv, a0);
            a1 = fmaf(x4.y, wv, a1);
            a2 = fmaf(x4.z, wv, a2);
            a3 = fmaf(x4.w, wv, a3);
        }
        float bb = fc_b[c];
        out[(rowbase + rg * 4 + 0) * VOCAB + c] = a0 + bb;
        out[(rowbase + rg * 4 + 1) * VOCAB + c] = a1 + bb;
        out[(rowbase + rg * 4 + 2) * VOCAB + c] = a2 + bb;
        out[(rowbase + rg * 4 + 3) * VOCAB + c] = a3 + bb;
    }
}

// ---------------------------------------------------------------------------
extern "C" void kernel_launch(void* const* d_in, const int* in_sizes, int n_in,
                              void* d_out, int out_size) {
    const int*   x      = (const int*)  d_in[0];
    const float* emb    = (const float*)d_in[1];
    const float* w_ih0  = (const float*)d_in[2];
    const float* b_ih0  = (const float*)d_in[3];
    const float* w_hh0  = (const float*)d_in[4];
    const float* b_hh0  = (const float*)d_in[5];
    const float* w_ih1  = (const float*)d_in[6];
    const float* b_ih1  = (const float*)d_in[7];
    const float* w_hh1  = (const float*)d_in[8];
    const float* b_hh1  = (const float*)d_in[9];
    const float* attn_w = (const float*)d_in[10];
    const float* attn_b = (const float*)d_in[11];
    const float* fc_w   = (const float*)d_in[12];
    const float* fc_b   = (const float*)d_in[13];
    float* out = (float*)d_out;

    const int QSMEM = (128 * 132 + 128 * 68) * 4;      // 102400
    const int ASMEM = (2 * 64 * KROW + 64 * 68) * 4;   // 83968
    const int FSMEM = (256 * 56 + 256 * 20) * 4;       // 77824
    cudaFuncSetAttribute((const void*)q_kernel,
                         cudaFuncAttributeMaxDynamicSharedMemorySize, QSMEM);
    cudaFuncSetAttribute((const void*)attn_kernel,
                         cudaFuncAttributeMaxDynamicSharedMemorySize, ASMEM);
    cudaFuncSetAttribute((const void*)fc_kernel,
                         cudaFuncAttributeMaxDynamicSharedMemorySize, FSMEM);

    tab0_kernel<<<VOCAB, HID>>>(emb, w_ih0, b_ih0, b_hh0);
    rnn_kernel<<<BB, 384>>>(x, w_hh0, w_ih1, b_ih1, w_hh1, b_hh1);
    q_kernel<<<(BB * TT) / 64, 256, QSMEM>>>(attn_w, attn_b);
    attn_kernel<<<dim3(BB, 16), 256, ASMEM>>>();   // LPT: qt = 15 - blockIdx.y
    fc_kernel<<<(BB * TT) / 16, 256, FSMEM>>>(fc_w, fc_b, out);
}